// round 1
// baseline (speedup 1.0000x reference)
#include <cuda_runtime.h>
#include <cuda_bf16.h>
#include <math.h>

// Problem constants
#define S_DIM 8
#define U_DIM 8
#define K_STEPS 12
#define NEG 17
#define Z_DIM 64
#define C_DIM 256
#define T_DIM 1140
#define LENGTH 1128            // T - K
#define SU 64                  // S*U
#define ITEMS_PER_K (SU * LENGTH)      // 72192
#define BLOCKS_PER_K (ITEMS_PER_K / 256) // 282 (exact)

// Scratch: Wc[k][su][l][zd]  -> 12*64*1128*64 floats = ~222 MB
__device__ float g_wc[(size_t)K_STEPS * SU * LENGTH * Z_DIM];
__device__ float g_loss[K_STEPS];
__device__ float g_acc[K_STEPS];

// ---------------------------------------------------------------------------
// Kernel 0: zero accumulators
// ---------------------------------------------------------------------------
__global__ void zero_accum_kernel() {
    int t = threadIdx.x;
    if (t < K_STEPS) { g_loss[t] = 0.f; g_acc[t] = 0.f; }
}

// ---------------------------------------------------------------------------
// Kernel 1: Wc = c_trunc @ W^T + b  for all k at once.
//   A: c rows (su,l) -> c[(su*1140 + l)*256 + cd],  l < 1128
//   B: W[(k*64+zd)*256 + cd]
//   out: g_wc[((k*64+su)*1128 + l)*64 + zd]
// Tiling: BM=64 (l), BN=64 (zd, one k per N-tile), BK=16. 256 thr, 4x4 micro.
// ---------------------------------------------------------------------------
#define BM 64
#define BN 64
#define BKK 16

__global__ __launch_bounds__(256) void wc_gemm_kernel(
    const float* __restrict__ c, const float* __restrict__ W,
    const float* __restrict__ b)
{
    const int bn = blockIdx.x;          // k index (N tile of 64 == one k)
    const int bm = blockIdx.y;          // 0 .. 64*18-1
    const int su = bm / 18;
    const int l0 = (bm % 18) * BM;

    const int tid = threadIdx.x;
    const int tx = tid & 15;            // 0..15  (zd/4 lane)
    const int ty = tid >> 4;            // 0..15  (l/4 lane)

    __shared__ float As[BKK][BM];
    __shared__ float Bs[BKK][BN];

    float acc[4][4];
#pragma unroll
    for (int i = 0; i < 4; i++)
#pragma unroll
        for (int j = 0; j < 4; j++) acc[i][j] = 0.f;

    const float* Arow = c + ((size_t)su * T_DIM + l0) * C_DIM;
    const float* Brow = W + (size_t)(bn * 64) * C_DIM;

    for (int k0 = 0; k0 < C_DIM; k0 += BKK) {
        // load A tile: 64 rows x 16 k  (1024 elems, 4 per thread)
#pragma unroll
        for (int e = tid; e < BM * BKK; e += 256) {
            int m = e >> 4, kk = e & 15;
            float v = 0.f;
            if (l0 + m < LENGTH) v = Arow[m * C_DIM + k0 + kk];
            As[kk][m] = v;
        }
        // load B tile: 64 cols x 16 k
#pragma unroll
        for (int e = tid; e < BN * BKK; e += 256) {
            int n = e >> 4, kk = e & 15;
            Bs[kk][n] = Brow[n * C_DIM + k0 + kk];
        }
        __syncthreads();

#pragma unroll
        for (int kk = 0; kk < BKK; kk++) {
            float4 av = *reinterpret_cast<const float4*>(&As[kk][ty * 4]);
            float4 bv = *reinterpret_cast<const float4*>(&Bs[kk][tx * 4]);
            float a[4] = {av.x, av.y, av.z, av.w};
            float bb[4] = {bv.x, bv.y, bv.z, bv.w};
#pragma unroll
            for (int i = 0; i < 4; i++)
#pragma unroll
                for (int j = 0; j < 4; j++) acc[i][j] += a[i] * bb[j];
        }
        __syncthreads();
    }

    // store with bias; out col base zd = tx*4 (16B aligned)
    float4 bias4 = *reinterpret_cast<const float4*>(&b[bn * 64 + tx * 4]);
#pragma unroll
    for (int i = 0; i < 4; i++) {
        int l = l0 + ty * 4 + i;
        if (l < LENGTH) {
            float4 o;
            o.x = acc[i][0] + bias4.x;
            o.y = acc[i][1] + bias4.y;
            o.z = acc[i][2] + bias4.z;
            o.w = acc[i][3] + bias4.w;
            size_t base = (((size_t)(bn * 64 + su) * LENGTH + l) * Z_DIM) + tx * 4;
            *reinterpret_cast<float4*>(&g_wc[base]) = o;
        }
    }
}

// ---------------------------------------------------------------------------
// Kernel 2: per-item scoring. One thread = one (k, su, l).
//   pos = <z[su, l+k+1], Wc> * 0.125
//   neg[n] = <z[s*8+bi, si+k+1], Wc> * 0.125
//   loss_i = logsumexp([pos,negs]) - pos ; acc_i = (no neg > pos)
// Each block lies entirely inside one k (72192 = 282*256).
// ---------------------------------------------------------------------------
__global__ __launch_bounds__(256) void cpc_score_kernel(
    const float* __restrict__ z,
    const int* __restrict__ batch_index,
    const int* __restrict__ seq_index)
{
    const int k = blockIdx.x / BLOCKS_PER_K;
    const int idx = (blockIdx.x % BLOCKS_PER_K) * 256 + threadIdx.x;
    const int su = idx / LENGTH;
    const int l = idx - su * LENGTH;
    const int s = su >> 3;
    const int u = su & 7;

    // load Wc vector (64 floats) into registers
    const float4* wcv = reinterpret_cast<const float4*>(
        g_wc + ((size_t)(k * SU + su) * LENGTH + l) * Z_DIM);
    float4 w[16];
    // pos dot while loading
    const float4* zp = reinterpret_cast<const float4*>(
        z + ((size_t)su * T_DIM + l + k + 1) * Z_DIM);
    float4 a = make_float4(0.f, 0.f, 0.f, 0.f);
#pragma unroll
    for (int i = 0; i < 16; i++) {
        w[i] = wcv[i];
        float4 zv = zp[i];
        a.x += w[i].x * zv.x; a.y += w[i].y * zv.y;
        a.z += w[i].z * zv.z; a.w += w[i].w * zv.w;
    }
    const float pos = (a.x + a.y + a.z + a.w) * 0.125f;

    const int* biP = batch_index + (k * U_DIM + u) * NEG;
    const int* siP = seq_index + ((size_t)((k * S_DIM + s) * U_DIM + u) * NEG) * LENGTH + l;

    float f[NEG];
    float m = pos;
#pragma unroll 1
    for (int n = 0; n < NEG; n++) {
        int bi = biP[n];
        int si = siP[(size_t)n * LENGTH];
        const float4* zn = reinterpret_cast<const float4*>(
            z + ((size_t)(s * U_DIM + bi) * T_DIM + si + k + 1) * Z_DIM);
        float4 acc2 = make_float4(0.f, 0.f, 0.f, 0.f);
#pragma unroll
        for (int i = 0; i < 16; i++) {
            float4 zv = zn[i];
            acc2.x += w[i].x * zv.x; acc2.y += w[i].y * zv.y;
            acc2.z += w[i].z * zv.z; acc2.w += w[i].w * zv.w;
        }
        float v = (acc2.x + acc2.y + acc2.z + acc2.w) * 0.125f;
        f[n] = v;
        m = fmaxf(m, v);
    }

    float sum = expf(pos - m);
    bool win = true;
#pragma unroll
    for (int n = 0; n < NEG; n++) {
        sum += expf(f[n] - m);
        if (f[n] > pos) win = false;
    }
    const float loss_i = (m + logf(sum)) - pos;
    const float acc_i = win ? 1.f : 0.f;

    // block reduction
    __shared__ float sl[256];
    __shared__ float sa[256];
    const int tid = threadIdx.x;
    sl[tid] = loss_i;
    sa[tid] = acc_i;
    __syncthreads();
#pragma unroll
    for (int s2 = 128; s2 > 0; s2 >>= 1) {
        if (tid < s2) { sl[tid] += sl[tid + s2]; sa[tid] += sa[tid + s2]; }
        __syncthreads();
    }
    if (tid == 0) {
        atomicAdd(&g_loss[k], sl[0]);
        atomicAdd(&g_acc[k], sa[0]);
    }
}

// ---------------------------------------------------------------------------
// Kernel 3: finalize. out[0] = mean_k(loss_k), out[1..12] = acc_k
// ---------------------------------------------------------------------------
__global__ void finalize_kernel(float* __restrict__ out, int out_size)
{
    int t = threadIdx.x;
    const float invN = 1.0f / (float)ITEMS_PER_K;
    if (t == 0) {
        float s = 0.f;
#pragma unroll
        for (int k = 0; k < K_STEPS; k++) s += g_loss[k];
        if (out_size >= 1) out[0] = s * invN / (float)K_STEPS;
    } else if (t <= K_STEPS) {
        if (out_size >= 1 + K_STEPS) out[t] = g_acc[t - 1] * invN;
    }
}

// ---------------------------------------------------------------------------
extern "C" void kernel_launch(void* const* d_in, const int* in_sizes, int n_in,
                              void* d_out, int out_size)
{
    const float* z = (const float*)d_in[0];
    const float* c = (const float*)d_in[1];
    const float* W = (const float*)d_in[2];
    const float* b = (const float*)d_in[3];
    const int* batch_index = (const int*)d_in[4];
    const int* seq_index = (const int*)d_in[5];
    float* out = (float*)d_out;

    zero_accum_kernel<<<1, 32>>>();

    dim3 gemm_grid(K_STEPS, SU * 18);   // (k, su*18 l-tiles)
    wc_gemm_kernel<<<gemm_grid, 256>>>(c, W, b);

    cpc_score_kernel<<<K_STEPS * BLOCKS_PER_K, 256>>>(z, batch_index, seq_index);

    finalize_kernel<<<1, 32>>>(out, out_size);
}

// round 2
// speedup vs baseline: 2.0109x; 2.0109x over previous
#include <cuda_runtime.h>
#include <cuda_bf16.h>
#include <cstdint>
#include <math.h>

// Problem constants
#define S_DIM 8
#define U_DIM 8
#define K_STEPS 12
#define NEG 17
#define Z_DIM 64
#define C_DIM 256
#define T_DIM 1140
#define LENGTH 1128            // T - K
#define SU 64                  // S*U
#define ITEMS_PER_K (SU * LENGTH)        // 72192
#define BLOCKS_PER_K (ITEMS_PER_K / 256) // 282 (exact)

// Scratch: Wc[k][su][l][zd]  -> 12*64*1128*64 floats = ~222 MB
__device__ float g_wc[(size_t)K_STEPS * SU * LENGTH * Z_DIM];
__device__ float g_loss[K_STEPS];
__device__ float g_acc[K_STEPS];

// ---------------------------------------------------------------------------
// Kernel 0: zero accumulators
// ---------------------------------------------------------------------------
__global__ void zero_accum_kernel() {
    int t = threadIdx.x;
    if (t < K_STEPS) { g_loss[t] = 0.f; g_acc[t] = 0.f; }
}

// ---------------------------------------------------------------------------
// TF32 tensor-core GEMM: Wc[k] = c_trunc @ W[k]^T + b[k]
//   Block: 128 (l) x 64 (zd = full N for one k), K=256 in BK=16 chunks,
//   double-buffered cp.async. 8 warps, 4(M) x 2(N); warp tile 32x32 via
//   m16n8k8 tf32 mma (2 m-frags x 4 n-frags).
// Smem rows padded to 20 floats -> all fragment gathers conflict-free.
// ---------------------------------------------------------------------------
#define BLK_M 128
#define BK 16
#define APAD 20

__device__ __forceinline__ void cp_async16(uint32_t dst, const void* src, bool pred) {
    int sz = pred ? 16 : 0;
    asm volatile("cp.async.cg.shared.global [%0], [%1], 16, %2;\n"
                 :: "r"(dst), "l"(src), "r"(sz));
}
__device__ __forceinline__ void cp_commit() {
    asm volatile("cp.async.commit_group;\n");
}
__device__ __forceinline__ uint32_t cvt_tf32(float v) {
    uint32_t x;
    asm volatile("cvt.rna.tf32.f32 %0, %1;\n" : "=r"(x) : "f"(v));
    return x;
}

__global__ __launch_bounds__(256) void wc_gemm_tf32(
    const float* __restrict__ c, const float* __restrict__ W,
    const float* __restrict__ b)
{
    __shared__ float As[2][BLK_M * APAD];   // 128 rows x 16 k (padded 20)
    __shared__ float Bs[2][Z_DIM * APAD];   // 64 n-rows x 16 k (padded 20)

    const int ltile = blockIdx.x;   // 0..8
    const int su    = blockIdx.y;   // 0..63
    const int k     = blockIdx.z;   // 0..11
    const int l0    = ltile * BLK_M;

    const int tid  = threadIdx.x;
    const int lane = tid & 31;
    const int wid  = tid >> 5;
    const int warpM = wid & 3;      // 0..3 -> m offset *32
    const int warpN = wid >> 2;     // 0..1 -> n offset *32

    const float* Abase = c + ((size_t)su * T_DIM + l0) * C_DIM;
    const float* Bbase = W + (size_t)k * Z_DIM * C_DIM;

    // A chunk mapping: 512 float4 chunks (128 rows x 4), 2 per thread
    const int ar0 = tid >> 1;                 // via idx = tid + i*256: row = idx/4
    // We'll compute inside the loader loop instead for clarity.

    float acc[2][4][4];
#pragma unroll
    for (int mf = 0; mf < 2; mf++)
#pragma unroll
        for (int nf = 0; nf < 4; nf++)
#pragma unroll
            for (int r = 0; r < 4; r++) acc[mf][nf][r] = 0.f;

    uint32_t sA[2], sB[2];
    sA[0] = (uint32_t)__cvta_generic_to_shared(&As[0][0]);
    sA[1] = (uint32_t)__cvta_generic_to_shared(&As[1][0]);
    sB[0] = (uint32_t)__cvta_generic_to_shared(&Bs[0][0]);
    sB[1] = (uint32_t)__cvta_generic_to_shared(&Bs[1][0]);

    // ---- tile loader (BK=16 slice starting at k0 into buffer bf) ----
    auto load_tiles = [&](int bf, int k0) {
#pragma unroll
        for (int i = 0; i < 2; i++) {
            int idx  = tid + i * 256;          // 0..511
            int row  = idx >> 2;               // 0..127
            int col4 = idx & 3;                // 0..3
            bool ok  = (l0 + row) < LENGTH;
            cp_async16(sA[bf] + (row * APAD + col4 * 4) * 4,
                       Abase + (size_t)row * C_DIM + k0 + col4 * 4, ok);
        }
        {
            int row  = tid >> 2;               // 0..63
            int col4 = tid & 3;
            cp_async16(sB[bf] + (row * APAD + col4 * 4) * 4,
                       Bbase + (size_t)row * C_DIM + k0 + col4 * 4, true);
        }
        cp_commit();
    };

    load_tiles(0, 0);

    const int mrow = lane >> 2;   // 0..7
    const int kcol = lane & 3;    // 0..3

    int buf = 0;
#pragma unroll 1
    for (int kb = 0; kb < C_DIM / BK; kb++) {
        if (kb < C_DIM / BK - 1) {
            load_tiles(buf ^ 1, (kb + 1) * BK);
            asm volatile("cp.async.wait_group 1;\n");
        } else {
            asm volatile("cp.async.wait_group 0;\n");
        }
        __syncthreads();

        const float* A = As[buf];
        const float* B = Bs[buf];
#pragma unroll
        for (int ks = 0; ks < 2; ks++) {
            const int kc = ks * 8 + kcol;
            uint32_t a[2][4], bb[4][2];
#pragma unroll
            for (int mf = 0; mf < 2; mf++) {
                int r = warpM * 32 + mf * 16 + mrow;
                a[mf][0] = cvt_tf32(A[r * APAD + kc]);
                a[mf][1] = cvt_tf32(A[(r + 8) * APAD + kc]);
                a[mf][2] = cvt_tf32(A[r * APAD + kc + 4]);
                a[mf][3] = cvt_tf32(A[(r + 8) * APAD + kc + 4]);
            }
#pragma unroll
            for (int nf = 0; nf < 4; nf++) {
                int cN = warpN * 32 + nf * 8 + mrow;
                bb[nf][0] = cvt_tf32(B[cN * APAD + kc]);
                bb[nf][1] = cvt_tf32(B[cN * APAD + kc + 4]);
            }
#pragma unroll
            for (int mf = 0; mf < 2; mf++)
#pragma unroll
                for (int nf = 0; nf < 4; nf++) {
                    asm volatile(
                        "mma.sync.aligned.m16n8k8.row.col.f32.tf32.tf32.f32 "
                        "{%0,%1,%2,%3}, {%4,%5,%6,%7}, {%8,%9}, {%0,%1,%2,%3};\n"
                        : "+f"(acc[mf][nf][0]), "+f"(acc[mf][nf][1]),
                          "+f"(acc[mf][nf][2]), "+f"(acc[mf][nf][3])
                        : "r"(a[mf][0]), "r"(a[mf][1]), "r"(a[mf][2]), "r"(a[mf][3]),
                          "r"(bb[nf][0]), "r"(bb[nf][1]));
                }
        }
        __syncthreads();
        buf ^= 1;
    }

    // ---- epilogue: bias + store to g_wc ----
    const size_t outBase = (size_t)(k * SU + su) * LENGTH * Z_DIM;
#pragma unroll
    for (int nf = 0; nf < 4; nf++) {
        int col = warpN * 32 + nf * 8 + kcol * 2;
        float2 bias = *reinterpret_cast<const float2*>(&b[k * Z_DIM + col]);
#pragma unroll
        for (int mf = 0; mf < 2; mf++) {
            int r0 = warpM * 32 + mf * 16 + mrow;
            int l_a = l0 + r0;
            if (l_a < LENGTH) {
                float2 o = make_float2(acc[mf][nf][0] + bias.x,
                                       acc[mf][nf][1] + bias.y);
                *reinterpret_cast<float2*>(&g_wc[outBase + (size_t)l_a * Z_DIM + col]) = o;
            }
            int l_b = l_a + 8;
            if (l_b < LENGTH) {
                float2 o = make_float2(acc[mf][nf][2] + bias.x,
                                       acc[mf][nf][3] + bias.y);
                *reinterpret_cast<float2*>(&g_wc[outBase + (size_t)l_b * Z_DIM + col]) = o;
            }
        }
    }
}

// ---------------------------------------------------------------------------
// Kernel 2: per-item scoring. One thread = one (k, su, l).
// ---------------------------------------------------------------------------
__global__ __launch_bounds__(256) void cpc_score_kernel(
    const float* __restrict__ z,
    const int* __restrict__ batch_index,
    const int* __restrict__ seq_index)
{
    const int k = blockIdx.x / BLOCKS_PER_K;
    const int idx = (blockIdx.x % BLOCKS_PER_K) * 256 + threadIdx.x;
    const int su = idx / LENGTH;
    const int l = idx - su * LENGTH;
    const int s = su >> 3;
    const int u = su & 7;

    // load Wc vector (64 floats) into registers; fuse pos dot
    const float4* wcv = reinterpret_cast<const float4*>(
        g_wc + ((size_t)(k * SU + su) * LENGTH + l) * Z_DIM);
    float4 w[16];
    const float4* zp = reinterpret_cast<const float4*>(
        z + ((size_t)su * T_DIM + l + k + 1) * Z_DIM);
    float4 a = make_float4(0.f, 0.f, 0.f, 0.f);
#pragma unroll
    for (int i = 0; i < 16; i++) {
        w[i] = wcv[i];
        float4 zv = zp[i];
        a.x += w[i].x * zv.x; a.y += w[i].y * zv.y;
        a.z += w[i].z * zv.z; a.w += w[i].w * zv.w;
    }
    const float pos = (a.x + a.y + a.z + a.w) * 0.125f;

    const int* biP = batch_index + (k * U_DIM + u) * NEG;
    const int* siP = seq_index + ((size_t)((k * S_DIM + s) * U_DIM + u) * NEG) * LENGTH + l;

    float f[NEG];
    float m = pos;
#pragma unroll 1
    for (int n = 0; n < NEG; n++) {
        int bi = biP[n];
        int si = siP[(size_t)n * LENGTH];
        const float4* zn = reinterpret_cast<const float4*>(
            z + ((size_t)(s * U_DIM + bi) * T_DIM + si + k + 1) * Z_DIM);
        float4 acc2 = make_float4(0.f, 0.f, 0.f, 0.f);
#pragma unroll
        for (int i = 0; i < 16; i++) {
            float4 zv = zn[i];
            acc2.x += w[i].x * zv.x; acc2.y += w[i].y * zv.y;
            acc2.z += w[i].z * zv.z; acc2.w += w[i].w * zv.w;
        }
        float v = (acc2.x + acc2.y + acc2.z + acc2.w) * 0.125f;
        f[n] = v;
        m = fmaxf(m, v);
    }

    float sum = expf(pos - m);
    bool win = true;
#pragma unroll
    for (int n = 0; n < NEG; n++) {
        sum += expf(f[n] - m);
        if (f[n] > pos) win = false;
    }
    const float loss_i = (m + logf(sum)) - pos;
    const float acc_i = win ? 1.f : 0.f;

    // block reduction
    __shared__ float sl[256];
    __shared__ float sa[256];
    const int tid = threadIdx.x;
    sl[tid] = loss_i;
    sa[tid] = acc_i;
    __syncthreads();
#pragma unroll
    for (int s2 = 128; s2 > 0; s2 >>= 1) {
        if (tid < s2) { sl[tid] += sl[tid + s2]; sa[tid] += sa[tid + s2]; }
        __syncthreads();
    }
    if (tid == 0) {
        atomicAdd(&g_loss[k], sl[0]);
        atomicAdd(&g_acc[k], sa[0]);
    }
}

// ---------------------------------------------------------------------------
// Kernel 3: finalize. out[0] = mean_k(loss_k), out[1..12] = acc_k
// ---------------------------------------------------------------------------
__global__ void finalize_kernel(float* __restrict__ out, int out_size)
{
    int t = threadIdx.x;
    const float invN = 1.0f / (float)ITEMS_PER_K;
    if (t == 0) {
        float s = 0.f;
#pragma unroll
        for (int k = 0; k < K_STEPS; k++) s += g_loss[k];
        if (out_size >= 1) out[0] = s * invN / (float)K_STEPS;
    } else if (t <= K_STEPS) {
        if (out_size >= 1 + K_STEPS) out[t] = g_acc[t - 1] * invN;
    }
}

// ---------------------------------------------------------------------------
extern "C" void kernel_launch(void* const* d_in, const int* in_sizes, int n_in,
                              void* d_out, int out_size)
{
    const float* z = (const float*)d_in[0];
    const float* c = (const float*)d_in[1];
    const float* W = (const float*)d_in[2];
    const float* b = (const float*)d_in[3];
    const int* batch_index = (const int*)d_in[4];
    const int* seq_index = (const int*)d_in[5];
    float* out = (float*)d_out;

    zero_accum_kernel<<<1, 32>>>();

    dim3 gemm_grid(9, SU, K_STEPS);   // (l-tiles of 128, su, k)
    wc_gemm_tf32<<<gemm_grid, 256>>>(c, W, b);

    cpc_score_kernel<<<K_STEPS * BLOCKS_PER_K, 256>>>(z, batch_index, seq_index);

    finalize_kernel<<<1, 32>>>(out, out_size);
}